// round 2
// baseline (speedup 1.0000x reference)
#include <cuda_runtime.h>

#define NHID 20
#define TPB  256
#define PPT  4   // points per thread = 2 f32x2 pairs

typedef unsigned long long u64;

// smem layout (u64 units)
#define OFF_SW   0                       // 6*400 hidden weights (splat pairs)
#define OFF_SB   (OFF_SW + 6*NHID*NHID)  // 6*20 hidden biases
#define OFF_SW0  (OFF_SB + 6*NHID)       // 20
#define OFF_SB0  (OFF_SW0 + NHID)        // 20
#define OFF_SW7  (OFF_SB0 + NHID)        // 20
#define OFF_SB7  (OFF_SW7 + NHID)        // 1
#define OFF_HSM  (OFF_SB7 + 1)           // 2*20*TPB activation staging
#define SMEM_U64 (OFF_HSM + 2*NHID*TPB)
#define SMEM_BYTES (SMEM_U64 * 8)

static __device__ __forceinline__ u64 pack2f(float lo, float hi) {
    u64 r;
    unsigned a = __float_as_uint(lo), b = __float_as_uint(hi);
    asm("mov.b64 %0, {%1, %2};" : "=l"(r) : "r"(a), "r"(b));
    return r;
}
static __device__ __forceinline__ void unpack2f(u64 v, float& lo, float& hi) {
    unsigned a, b;
    asm("mov.b64 {%0, %1}, %2;" : "=r"(a), "=r"(b) : "l"(v));
    lo = __uint_as_float(a);
    hi = __uint_as_float(b);
}
static __device__ __forceinline__ u64 fma2(u64 a, u64 b, u64 c) {
    u64 d;
    asm("fma.rn.f32x2 %0, %1, %2, %3;" : "=l"(d) : "l"(a), "l"(b), "l"(c));
    return d;
}
static __device__ __forceinline__ u64 mul2(u64 a, u64 b) {
    u64 d;
    asm("mul.rn.f32x2 %0, %1, %2;" : "=l"(d) : "l"(a), "l"(b));
    return d;
}
static __device__ __forceinline__ u64 add2(u64 a, u64 b) {
    u64 d;
    asm("add.rn.f32x2 %0, %1, %2;" : "=l"(d) : "l"(a), "l"(b));
    return d;
}
static __device__ __forceinline__ float ex2f(float x) {
    float r;
    asm("ex2.approx.f32 %0, %1;" : "=f"(r) : "f"(x));
    return r;
}
static __device__ __forceinline__ float rcpf(float x) {
    float r;
    asm("rcp.approx.f32 %0, %1;" : "=f"(r) : "f"(x));
    return r;
}

// silu on a packed pair: x * 1/(1+e^-x).
// 3 f32x2 fma-pipe ops + 4 MUFU; pack/unpack movs mostly fold into reg pairs.
static __device__ __forceinline__ u64 silu2(u64 x2, u64 negl2e2, u64 one2) {
    u64 m = mul2(x2, negl2e2);         // -x*log2(e), both lanes
    float mlo, mhi; unpack2f(m, mlo, mhi);
    u64 e = pack2f(ex2f(mlo), ex2f(mhi));   // e^-x
    u64 d = add2(e, one2);                  // 1 + e^-x
    float dlo, dhi; unpack2f(d, dlo, dhi);
    u64 r = pack2f(rcpf(dlo), rcpf(dhi));   // sigmoid
    return mul2(x2, r);
}

__global__ void __launch_bounds__(TPB, 2)
SpringEquationNN_kernel(
    const float* __restrict__ t,
    const float* __restrict__ W0, const float* __restrict__ b0,
    const float* __restrict__ W1, const float* __restrict__ b1,
    const float* __restrict__ W2, const float* __restrict__ b2,
    const float* __restrict__ W3, const float* __restrict__ b3,
    const float* __restrict__ W4, const float* __restrict__ b4,
    const float* __restrict__ W5, const float* __restrict__ b5,
    const float* __restrict__ W6, const float* __restrict__ b6,
    const float* __restrict__ W7, const float* __restrict__ b7,
    float* __restrict__ out, int n)
{
    extern __shared__ u64 dyn[];
    u64* sW  = dyn + OFF_SW;
    u64* sB  = dyn + OFF_SB;
    u64* sW0 = dyn + OFF_SW0;
    u64* sB0 = dyn + OFF_SB0;
    u64* sW7 = dyn + OFF_SW7;
    u64* sB7 = dyn + OFF_SB7;
    u64* hsm = dyn + OFF_HSM;

    const int tid = threadIdx.x;

    for (int i = tid; i < NHID; i += TPB) {
        sW0[i] = pack2f(W0[i], W0[i]);
        sB0[i] = pack2f(b0[i], b0[i]);
        sW7[i] = pack2f(W7[i], W7[i]);
    }
    for (int i = tid; i < 6 * NHID * NHID; i += TPB) {
        int l = i / (NHID * NHID);
        int r = i - l * (NHID * NHID);
        float w;
        switch (l) {
            case 0: w = W1[r]; break;
            case 1: w = W2[r]; break;
            case 2: w = W3[r]; break;
            case 3: w = W4[r]; break;
            case 4: w = W5[r]; break;
            default: w = W6[r]; break;
        }
        sW[i] = pack2f(w, w);
    }
    for (int i = tid; i < 6 * NHID; i += TPB) {
        int l = i / NHID;
        int r = i - l * NHID;
        float w;
        switch (l) {
            case 0: w = b1[r]; break;
            case 1: w = b2[r]; break;
            case 2: w = b3[r]; break;
            case 3: w = b4[r]; break;
            case 4: w = b5[r]; break;
            default: w = b6[r]; break;
        }
        sB[i] = pack2f(w, w);
    }
    if (tid == 0) sB7[0] = pack2f(b7[0], b7[0]);
    __syncthreads();

    const u64 NEGL2E2 = pack2f(-1.442695041f, -1.442695041f);
    const u64 ONE2    = pack2f(1.0f, 1.0f);

    const int base = (blockIdx.x * TPB + tid) * PPT;
    if (base >= n) return;

    float tx, ty, tz, tw;
    if (base + PPT <= n) {
        float4 v = *reinterpret_cast<const float4*>(t + base);
        tx = v.x; ty = v.y; tz = v.z; tw = v.w;
    } else {
        tx = t[base];
        ty = (base + 1 < n) ? t[base + 1] : 0.0f;
        tz = (base + 2 < n) ? t[base + 2] : 0.0f;
        tw = (base + 3 < n) ? t[base + 3] : 0.0f;
    }
    const u64 x0 = pack2f(tx, ty);
    const u64 x1 = pack2f(tz, tw);

    // Layer 0: 1 -> 20, result staged to private smem slots
    #pragma unroll
    for (int j = 0; j < NHID; j++) {
        u64 w = sW0[j], bb = sB0[j];
        hsm[j * TPB + tid]          = silu2(fma2(x0, w, bb), NEGL2E2, ONE2);
        hsm[(NHID + j) * TPB + tid] = silu2(fma2(x1, w, bb), NEGL2E2, ONE2);
    }

    // Hidden layers: k-outer accumulation; only 40 u64 accumulators live.
    for (int l = 0; l < 6; l++) {
        const u64* wl = &sW[l * NHID * NHID];
        const u64* bl = &sB[l * NHID];
        u64 a0[NHID], a1[NHID];
        #pragma unroll
        for (int j = 0; j < NHID; j++) {
            u64 bb = bl[j];
            a0[j] = bb;
            a1[j] = bb;
        }
        #pragma unroll
        for (int k = 0; k < NHID; k++) {
            u64 h0 = hsm[k * TPB + tid];
            u64 h1 = hsm[(NHID + k) * TPB + tid];
            #pragma unroll
            for (int j = 0; j < NHID; j++) {
                u64 w = wl[j * NHID + k];
                a0[j] = fma2(h0, w, a0[j]);
                a1[j] = fma2(h1, w, a1[j]);
            }
        }
        // In-place overwrite is safe: all reads of layer l-1 happened above,
        // and hsm slots are thread-private.
        #pragma unroll
        for (int j = 0; j < NHID; j++) {
            hsm[j * TPB + tid]          = silu2(a0[j], NEGL2E2, ONE2);
            hsm[(NHID + j) * TPB + tid] = silu2(a1[j], NEGL2E2, ONE2);
        }
    }

    // Output layer: 20 -> 1
    u64 acc0 = sB7[0];
    u64 acc1 = acc0;
    #pragma unroll
    for (int k = 0; k < NHID; k++) {
        u64 w = sW7[k];
        acc0 = fma2(hsm[k * TPB + tid], w, acc0);
        acc1 = fma2(hsm[(NHID + k) * TPB + tid], w, acc1);
    }

    float o0, o1, o2, o3;
    unpack2f(acc0, o0, o1);
    unpack2f(acc1, o2, o3);
    if (base + PPT <= n) {
        *reinterpret_cast<float4*>(out + base) = make_float4(o0, o1, o2, o3);
    } else {
        out[base] = o0;
        if (base + 1 < n) out[base + 1] = o1;
        if (base + 2 < n) out[base + 2] = o2;
        if (base + 3 < n) out[base + 3] = o3;
    }
}

extern "C" void kernel_launch(void* const* d_in, const int* in_sizes, int n_in,
                              void* d_out, int out_size)
{
    const float* t  = (const float*)d_in[0];
    const float* W0 = (const float*)d_in[1];
    const float* b0 = (const float*)d_in[2];
    const float* W1 = (const float*)d_in[3];
    const float* b1 = (const float*)d_in[4];
    const float* W2 = (const float*)d_in[5];
    const float* b2 = (const float*)d_in[6];
    const float* W3 = (const float*)d_in[7];
    const float* b3 = (const float*)d_in[8];
    const float* W4 = (const float*)d_in[9];
    const float* b4 = (const float*)d_in[10];
    const float* W5 = (const float*)d_in[11];
    const float* b5 = (const float*)d_in[12];
    const float* W6 = (const float*)d_in[13];
    const float* b6 = (const float*)d_in[14];
    const float* W7 = (const float*)d_in[15];
    const float* b7 = (const float*)d_in[16];

    const int n = in_sizes[0];
    float* out = (float*)d_out;

    static bool attr_set = false;
    if (!attr_set) {
        cudaFuncSetAttribute(SpringEquationNN_kernel,
                             cudaFuncAttributeMaxDynamicSharedMemorySize,
                             SMEM_BYTES);
        attr_set = true;
    }

    const int pts_per_block = TPB * PPT;
    const int grid = (n + pts_per_block - 1) / pts_per_block;

    SpringEquationNN_kernel<<<grid, TPB, SMEM_BYTES>>>(
        t, W0, b0, W1, b1, W2, b2, W3, b3,
        W4, b4, W5, b5, W6, b6, W7, b7, out, n);
}

// round 3
// speedup vs baseline: 1.1836x; 1.1836x over previous
#include <cuda_runtime.h>

#define NHID 20
#define TPB  256
#define PPT  2   // points per thread = 1 f32x2 pair

typedef unsigned long long u64;

static __device__ __forceinline__ u64 pack2f(float lo, float hi) {
    u64 r;
    unsigned a = __float_as_uint(lo), b = __float_as_uint(hi);
    asm("mov.b64 %0, {%1, %2};" : "=l"(r) : "r"(a), "r"(b));
    return r;
}
static __device__ __forceinline__ void unpack2f(u64 v, float& lo, float& hi) {
    unsigned a, b;
    asm("mov.b64 {%0, %1}, %2;" : "=r"(a), "=r"(b) : "l"(v));
    lo = __uint_as_float(a);
    hi = __uint_as_float(b);
}
static __device__ __forceinline__ u64 fma2(u64 a, u64 b, u64 c) {
    u64 d;
    asm("fma.rn.f32x2 %0, %1, %2, %3;" : "=l"(d) : "l"(a), "l"(b), "l"(c));
    return d;
}
static __device__ __forceinline__ u64 mul2(u64 a, u64 b) {
    u64 d;
    asm("mul.rn.f32x2 %0, %1, %2;" : "=l"(d) : "l"(a), "l"(b));
    return d;
}
static __device__ __forceinline__ u64 add2(u64 a, u64 b) {
    u64 d;
    asm("add.rn.f32x2 %0, %1, %2;" : "=l"(d) : "l"(a), "l"(b));
    return d;
}
static __device__ __forceinline__ float ex2f(float x) {
    float r;
    asm("ex2.approx.f32 %0, %1;" : "=f"(r) : "f"(x));
    return r;
}
static __device__ __forceinline__ float rcpf(float x) {
    float r;
    asm("rcp.approx.f32 %0, %1;" : "=f"(r) : "f"(x));
    return r;
}

// silu on a packed pair: x * 1/(1+e^-x).  3 f32x2 fma-pipe ops + 4 MUFU.
static __device__ __forceinline__ u64 silu2(u64 x2, u64 negl2e2, u64 one2) {
    u64 m = mul2(x2, negl2e2);              // -x*log2(e)
    float mlo, mhi; unpack2f(m, mlo, mhi);
    u64 e = pack2f(ex2f(mlo), ex2f(mhi));   // e^-x
    u64 d = add2(e, one2);                  // 1 + e^-x
    float dlo, dhi; unpack2f(d, dlo, dhi);
    u64 r = pack2f(rcpf(dlo), rcpf(dhi));   // sigmoid
    return mul2(x2, r);
}

__global__ void __launch_bounds__(TPB, 2)   // cap regs at 128 -> 4 warps/SMSP
SpringEquationNN_kernel(
    const float* __restrict__ t,
    const float* __restrict__ W0, const float* __restrict__ b0,
    const float* __restrict__ W1, const float* __restrict__ b1,
    const float* __restrict__ W2, const float* __restrict__ b2,
    const float* __restrict__ W3, const float* __restrict__ b3,
    const float* __restrict__ W4, const float* __restrict__ b4,
    const float* __restrict__ W5, const float* __restrict__ b5,
    const float* __restrict__ W6, const float* __restrict__ b6,
    const float* __restrict__ W7, const float* __restrict__ b7,
    float* __restrict__ out, int n)
{
    // Weights duplicated as {w,w} pairs: one LDS.64 broadcast feeds FMA2.
    __shared__ u64 sW0[NHID], sB0[NHID], sW7[NHID];
    __shared__ u64 sW[6 * NHID * NHID];
    __shared__ u64 sB[6 * NHID];
    __shared__ float sb7;

    const int tid = threadIdx.x;

    for (int i = tid; i < NHID; i += TPB) {
        sW0[i] = pack2f(W0[i], W0[i]);
        sB0[i] = pack2f(b0[i], b0[i]);
        sW7[i] = pack2f(W7[i], W7[i]);
    }
    for (int i = tid; i < 6 * NHID * NHID; i += TPB) {
        int l = i / (NHID * NHID);
        int r = i - l * (NHID * NHID);
        float w;
        switch (l) {
            case 0: w = W1[r]; break;
            case 1: w = W2[r]; break;
            case 2: w = W3[r]; break;
            case 3: w = W4[r]; break;
            case 4: w = W5[r]; break;
            default: w = W6[r]; break;
        }
        sW[i] = pack2f(w, w);
    }
    for (int i = tid; i < 6 * NHID; i += TPB) {
        int l = i / NHID;
        int r = i - l * NHID;
        float w;
        switch (l) {
            case 0: w = b1[r]; break;
            case 1: w = b2[r]; break;
            case 2: w = b3[r]; break;
            case 3: w = b4[r]; break;
            case 4: w = b5[r]; break;
            default: w = b6[r]; break;
        }
        sB[i] = pack2f(w, w);
    }
    if (tid == 0) sb7 = b7[0];
    __syncthreads();

    const u64 NEGL2E2 = pack2f(-1.442695041f, -1.442695041f);
    const u64 ONE2    = pack2f(1.0f, 1.0f);

    const int base = (blockIdx.x * TPB + tid) * PPT;
    if (base >= n) return;

    float tx = t[base];
    float ty = (base + 1 < n) ? t[base + 1] : 0.0f;
    const u64 x0 = pack2f(tx, ty);

    u64 h[NHID], hn[NHID];

    // Layer 0: 1 -> 20
    #pragma unroll
    for (int j = 0; j < NHID; j++)
        h[j] = silu2(fma2(x0, sW0[j], sB0[j]), NEGL2E2, ONE2);

    // Hidden layers 1..6: 20 -> 20
    for (int l = 0; l < 6; l++) {
        const u64* wl = &sW[l * NHID * NHID];
        const u64* bl = &sB[l * NHID];
        #pragma unroll
        for (int j = 0; j < NHID; j++) {
            u64 a = bl[j];
            #pragma unroll
            for (int k = 0; k < NHID; k++)
                a = fma2(h[k], wl[j * NHID + k], a);
            hn[j] = silu2(a, NEGL2E2, ONE2);
        }
        #pragma unroll
        for (int j = 0; j < NHID; j++)
            h[j] = hn[j];
    }

    // Output layer: 20 -> 1
    u64 a = pack2f(sb7, sb7);
    #pragma unroll
    for (int k = 0; k < NHID; k++)
        a = fma2(h[k], sW7[k], a);

    float o0, o1;
    unpack2f(a, o0, o1);
    out[base] = o0;
    if (base + 1 < n) out[base + 1] = o1;
}

extern "C" void kernel_launch(void* const* d_in, const int* in_sizes, int n_in,
                              void* d_out, int out_size)
{
    const float* t  = (const float*)d_in[0];
    const float* W0 = (const float*)d_in[1];
    const float* b0 = (const float*)d_in[2];
    const float* W1 = (const float*)d_in[3];
    const float* b1 = (const float*)d_in[4];
    const float* W2 = (const float*)d_in[5];
    const float* b2 = (const float*)d_in[6];
    const float* W3 = (const float*)d_in[7];
    const float* b3 = (const float*)d_in[8];
    const float* W4 = (const float*)d_in[9];
    const float* b4 = (const float*)d_in[10];
    const float* W5 = (const float*)d_in[11];
    const float* b5 = (const float*)d_in[12];
    const float* W6 = (const float*)d_in[13];
    const float* b6 = (const float*)d_in[14];
    const float* W7 = (const float*)d_in[15];
    const float* b7 = (const float*)d_in[16];

    const int n = in_sizes[0];
    float* out = (float*)d_out;

    const int pts_per_block = TPB * PPT;
    const int grid = (n + pts_per_block - 1) / pts_per_block;

    SpringEquationNN_kernel<<<grid, TPB>>>(
        t, W0, b0, W1, b1, W2, b2, W3, b3,
        W4, b4, W5, b5, W6, b6, W7, b7, out, n);
}